// round 4
// baseline (speedup 1.0000x reference)
#include <cuda_runtime.h>

#define HID 64
#define CAP_ROWS 24000   // max T+1 rows for the precomputed input projection

typedef unsigned long long u64;

__device__ float g_xc[CAP_ROWS * 256];   // xc[t][j] = dcon_j + Wx_j . target[t-1]

__device__ __forceinline__ u64 pack2(float lo, float hi) {
    u64 r; asm("mov.b64 %0, {%1, %2};" : "=l"(r) : "f"(lo), "f"(hi)); return r;
}
__device__ __forceinline__ void unpack2(u64 v, float& lo, float& hi) {
    asm("mov.b64 {%0, %1}, %2;" : "=f"(lo), "=f"(hi) : "l"(v));
}
__device__ __forceinline__ void ffma2(u64& d, u64 a, u64 b) {
    asm("fma.rn.f32x2 %0, %1, %2, %0;" : "+l"(d) : "l"(a), "l"(b));
}
__device__ __forceinline__ u64 fadd2(u64 a, u64 b) {
    u64 r; asm("add.rn.f32x2 %0, %1, %2;" : "=l"(r) : "l"(a), "l"(b)); return r;
}
__device__ __forceinline__ float tanh_fast(float x) {
    return __fdividef(2.0f, 1.0f + __expf(-2.0f * x)) - 1.0f;
}

// ---------- precompute kernel: input projection for all steps ----------
__global__ void xc_precompute(const float* __restrict__ W_ih0,
                              const float* __restrict__ b_ih0,
                              const float* __restrict__ b_hh0,
                              const float* __restrict__ diff,
                              const float* __restrict__ target, int T)
{
    int j = threadIdx.x;
    int g = j & 3, m = j >> 2;
    int r = g * HID + m;                  // original (torch) gate row for this thread
    float w[8];
    #pragma unroll
    for (int i = 0; i < 8; i++) w[i] = W_ih0[r * 14 + i];
    float dcon = b_ih0[r] + b_hh0[r];
    #pragma unroll
    for (int i = 0; i < 6; i++) dcon += diff[i] * W_ih0[r * 14 + 8 + i];

    for (int t = 1 + blockIdx.x; t <= T; t += gridDim.x) {
        const float* tg = target + (t - 1) * 8;
        float s = dcon;
        #pragma unroll
        for (int i = 0; i < 8; i++) s += w[i] * tg[i];
        g_xc[t * 256 + j] = s;
    }
}

// ---------- main recurrent kernel ----------
__global__ __launch_bounds__(256, 1) void decoder_lstm_kernel(
    const float* __restrict__ h0_in, const float* __restrict__ c0_in,
    const float* __restrict__ W_hh0,
    const float* __restrict__ b_ih0, const float* __restrict__ b_hh0,
    const float* __restrict__ W_ih1, const float* __restrict__ W_hh1,
    const float* __restrict__ b_ih1, const float* __restrict__ b_hh1,
    const float* __restrict__ W_hid, const float* __restrict__ b_hid,
    const float* __restrict__ W_out, const float* __restrict__ b_out,
    float* __restrict__ out, int T)
{
    __shared__ __align__(16) float sh_h[2][128];     // [parity][h0(0..63) | h1(64..127)]
    __shared__ __align__(16) u64   sh_Wcp[32 * 8];   // fused head, packed pairs [kk][o]
    __shared__ float sh_bc[8];

    const int j    = threadIdx.x;
    const int g    = j & 3;           // gate: 0=i,1=f,2=g,3=o
    const int m    = j >> 2;          // hidden index 0..63
    const int r    = g * HID + m;     // original weight row
    const int lane = j & 31;
    const int base = lane & ~3;

    // unified activation: act(x) = aa / (1 + exp(-ab*x)) + ac   (sig or tanh)
    const float aa = (g == 2) ? 2.0f : 1.0f;
    const float ab = aa;
    const float ac = (g == 2) ? -1.0f : 0.0f;

    // ---- register-resident packed recurrent weights (row r of each matrix) ----
    u64 whh0p[32], wih1p[32], whh1p[32];
    #pragma unroll
    for (int k = 0; k < 32; k++) whh0p[k] = pack2(W_hh0[r * HID + 2 * k], W_hh0[r * HID + 2 * k + 1]);
    #pragma unroll
    for (int k = 0; k < 32; k++) wih1p[k] = pack2(W_ih1[r * HID + 2 * k], W_ih1[r * HID + 2 * k + 1]);
    #pragma unroll
    for (int k = 0; k < 32; k++) whh1p[k] = pack2(W_hh1[r * HID + 2 * k], W_hh1[r * HID + 2 * k + 1]);

    const float b1c   = b_ih1[r] + b_hh1[r];
    const float b0sum = b_ih0[r] + b_hh0[r];

    // ---- fused head Wc = W_out @ W_hid (packed), bias bc ----
    {
        int kk = j >> 3, o = j & 7;
        float lo = 0.0f, hi = 0.0f;
        for (int mm = 0; mm < 32; mm++) {
            lo += W_out[o * 32 + mm] * W_hid[mm * HID + 2 * kk];
            hi += W_out[o * 32 + mm] * W_hid[mm * HID + 2 * kk + 1];
        }
        sh_Wcp[kk * 8 + o] = pack2(lo, hi);
        if (j < 8) {
            float s = b_out[j];
            for (int mm = 0; mm < 32; mm++) s += W_out[j * 32 + mm] * b_hid[mm];
            sh_bc[j] = s;
        }
    }

    // ---- initial state ----
    float c0 = 0.0f, c1 = 0.0f;
    if (g == 0) c0 = c0_in[m];
    if (g == 1) c1 = c0_in[HID + m];
    if (j < HID)             sh_h[0][j] = h0_in[j];            // h0 init
    if (j >= HID && j < 128) sh_h[0][j] = h0_in[j];            // h1(-1) init
    __syncthreads();

    // ---- prologue: h0(0) from x(0)=zeros -> input part = b0sum ----
    {
        const ulonglong2* hq = (const ulonglong2*)&sh_h[0][0];
        u64 a0 = 0, a1 = 0;
        #pragma unroll
        for (int kk = 0; kk < 16; kk++) {
            ulonglong2 ha = hq[kk];
            ffma2(a0, whh0p[2 * kk],     ha.x);
            ffma2(a1, whh0p[2 * kk + 1], ha.y);
        }
        float alo, ahi; unpack2(fadd2(a0, a1), alo, ahi);
        float g0v = b0sum + alo + ahi;
        float t0 = __expf(-ab * g0v);
        float A0 = __fdividef(aa, 1.0f + t0) + ac;
        float f0b = __shfl_sync(0xffffffffu, A0, base + 1);
        float f0c = __shfl_sync(0xffffffffu, A0, base + 2);
        float f0d = __shfl_sync(0xffffffffu, A0, base + 3);
        __syncthreads();                       // all dots done before overwrite
        if (g == 0) {
            c0 = f0b * c0 + A0 * f0c;
            sh_h[0][m] = f0d * tanh_fast(c0);  // h0(0), same parity buffer
        }
        __syncthreads();
    }

    float xc_cur = g_xc[1 * 256 + j];          // xc(1), used at k=0

    // ---- main loop: iter k computes g0(k+1), g1(k); updates h0(k+1), h1(k); out(k-1) ----
    for (int k = 0; k < T; k++) {
        const int p = k & 1;
        const ulonglong2* h0q2 = (const ulonglong2*)&sh_h[p][0];
        const ulonglong2* h1q2 = (const ulonglong2*)&sh_h[p][64];

        // prefetch xc for next iteration (row clamped to T)
        int tr = k + 2; if (tr > T) tr = T;
        float xc_nx = __ldg(&g_xc[tr * 256 + j]);

        // ===== dots (one fat phase, 96 FFMA2) =====
        u64 a0 = 0, a1 = 0, q0 = 0, q1 = 0, p0 = 0, p1 = 0;
        #pragma unroll
        for (int kk = 0; kk < 16; kk++) {
            ulonglong2 ha = h0q2[kk];
            ffma2(a0, whh0p[2 * kk],     ha.x);
            ffma2(a1, whh0p[2 * kk + 1], ha.y);
            ffma2(q0, wih1p[2 * kk],     ha.x);
            ffma2(q1, wih1p[2 * kk + 1], ha.y);
            ulonglong2 hb = h1q2[kk];
            ffma2(p0, whh1p[2 * kk],     hb.x);
            ffma2(p1, whh1p[2 * kk + 1], hb.y);
        }
        float alo, ahi, glo, ghi;
        unpack2(fadd2(a0, a1), alo, ahi);
        unpack2(fadd2(fadd2(q0, q1), fadd2(p0, p1)), glo, ghi);
        float g0v = xc_cur + alo + ahi;        // layer0 gate, step k+1
        float g1v = b1c + glo + ghi;           // layer1 gate, step k
        xc_cur = xc_nx;

        // ===== branchless activations =====
        float e0 = __expf(-ab * g0v);
        float A0 = __fdividef(aa, 1.0f + e0) + ac;
        float e1 = __expf(-ab * g1v);
        float A1 = __fdividef(aa, 1.0f + e1) + ac;

        // ===== intra-warp gate gather =====
        float f0b = __shfl_sync(0xffffffffu, A0, base + 1);
        float f0c = __shfl_sync(0xffffffffu, A0, base + 2);
        float f0d = __shfl_sync(0xffffffffu, A0, base + 3);
        float f1a = __shfl_sync(0xffffffffu, A1, base + 0);
        float f1c = __shfl_sync(0xffffffffu, A1, base + 2);
        float f1d = __shfl_sync(0xffffffffu, A1, base + 3);

        // ===== branchless c/h update (lane 4m: layer0, lane 4m+1: layer1) =====
        float Sf = (g == 0) ? f0b : A1;
        float Si = (g == 0) ? A0  : f1a;
        float Sg = (g == 0) ? f0c : f1c;
        float So = (g == 0) ? f0d : f1d;
        float cs = (g == 0) ? c0  : c1;
        cs = Sf * cs + Si * Sg;
        float hn = So * tanh_fast(cs);
        if (g == 0 && k < T - 1) { c0 = cs; sh_h[p ^ 1][m] = hn; }
        if (g == 1)              { c1 = cs; sh_h[p ^ 1][64 + m] = hn; }

        // ===== FC head for out(k-1) in warp 0 (fills its MUFU bubbles) =====
        if (j < 32) {
            int half = g & 1, o = m;           // lanes duplicate halves pairwise
            const u64* h1q = (const u64*)&sh_h[p][64];
            u64 f0 = 0, f1 = 0;
            #pragma unroll
            for (int kk = 0; kk < 16; kk++) {
                int idx = half * 16 + kk;
                ffma2((kk & 1) ? f1 : f0, sh_Wcp[idx * 8 + o], h1q[idx]);
            }
            float flo, fhi; unpack2(fadd2(f0, f1), flo, fhi);
            float part = flo + fhi;
            float other = __shfl_xor_sync(0xffffffffu, part, 1);
            if (g == 3 && k > 0)
                out[(k - 1) * 8 + o] = rintf(sh_bc[o] + part + other);
        }

        __syncthreads();   // the single per-step barrier
    }

    // ---- epilogue: out(T-1) + finals ----
    const int pe = T & 1;                       // h1(T-1) lives in buffer pe
    if (j < 8) {
        const u64* h1q = (const u64*)&sh_h[pe][64];
        u64 f0 = 0, f1 = 0;
        #pragma unroll
        for (int kk = 0; kk < 32; kk++)
            ffma2((kk & 1) ? f1 : f0, sh_Wcp[kk * 8 + j], h1q[kk]);
        float flo, fhi; unpack2(fadd2(f0, f1), flo, fhi);
        out[(T - 1) * 8 + j] = rintf(sh_bc[j] + flo + fhi);
    }
    // finals: h_final = [h0(T-1); h1(T-1)], c_final = [c0(T-1); c1(T-1)]
    if (j < HID)             out[T * 8 + j] = sh_h[(T - 1) & 1][j];
    if (j >= HID && j < 128) out[T * 8 + j] = sh_h[pe][j];
    if (g == 0) out[T * 8 + 128 + m] = c0;
    if (g == 1) out[T * 8 + 192 + m] = c1;
}

extern "C" void kernel_launch(void* const* d_in, const int* in_sizes, int n_in,
                              void* d_out, int out_size) {
    const float* h0_in  = (const float*)d_in[1];
    const float* c0_in  = (const float*)d_in[2];
    const float* diff   = (const float*)d_in[3];
    const float* target = (const float*)d_in[4];
    const float* W_ih0  = (const float*)d_in[5];
    const float* W_hh0  = (const float*)d_in[6];
    const float* b_ih0  = (const float*)d_in[7];
    const float* b_hh0  = (const float*)d_in[8];
    const float* W_ih1  = (const float*)d_in[9];
    const float* W_hh1  = (const float*)d_in[10];
    const float* b_ih1  = (const float*)d_in[11];
    const float* b_hh1  = (const float*)d_in[12];
    const float* W_hid  = (const float*)d_in[13];
    const float* b_hid  = (const float*)d_in[14];
    const float* W_out  = (const float*)d_in[15];
    const float* b_out  = (const float*)d_in[16];

    int T = in_sizes[4] / 8;
    if (T + 1 > CAP_ROWS) T = CAP_ROWS - 1;   // safety clamp (dataset T=20000)

    xc_precompute<<<256, 256>>>(W_ih0, b_ih0, b_hh0, diff, target, T);

    decoder_lstm_kernel<<<1, 256>>>(
        h0_in, c0_in,
        W_hh0, b_ih0, b_hh0,
        W_ih1, W_hh1, b_ih1, b_hh1,
        W_hid, b_hid, W_out, b_out,
        (float*)d_out, T);
}